// round 2
// baseline (speedup 1.0000x reference)
#include <cuda_runtime.h>
#include <cstddef>

#define AGENTS 8192
#define FDIM   128
#define PDIM   16
#define EDGES  262144

// Scratch: packed per-row vectors.
// g_p[i] = [ alpha_i * nf_i (128) | (gamma_i/F) * diff_i (128) ]   (src side)
// g_q[i] = [ nf_i (128)           | diff_i (128) ]                 (dst side)
__device__ float g_p[(size_t)AGENTS * 2 * FDIM];
__device__ float g_q[(size_t)AGENTS * 2 * FDIM];
__device__ float g_beta[AGENTS];

// CSR-by-src scratch
__device__ int g_act_cnt[AGENTS];
__device__ int g_cost_cnt[AGENTS];
__device__ int g_act_off[AGENTS];
__device__ int g_cost_off[AGENTS];
__device__ int g_act_cur[AGENTS];
__device__ int g_cost_cur[AGENTS];
__device__ int g_act_dst[EDGES];
__device__ int g_cost_dst[EDGES];

// ---------------------------------------------------------------------------
// Kernel 1: per-row prep. One 128-thread block per row.
// ---------------------------------------------------------------------------
__global__ void __launch_bounds__(128) prep_kernel(
    const float* __restrict__ feature,
    const float* __restrict__ next_feature,
    const float* __restrict__ persona,
    const float* __restrict__ alpha,
    const float* __restrict__ beta,
    const float* __restrict__ gamma)
{
    const int row = blockIdx.x;
    const int tid = threadIdx.x;  // 0..127

    float a = 0.f, b = 0.f, g = 0.f;
#pragma unroll
    for (int k = 0; k < PDIM; k++) {
        float pv = persona[row * PDIM + k];
        a = fmaf(pv, alpha[k], a);
        b = fmaf(pv, beta[k],  b);
        g = fmaf(pv, gamma[k], g);
    }

    const float f   = feature[(size_t)row * FDIM + tid];
    const float nf0 = next_feature[(size_t)row * FDIM + tid];
    const float diff = f - nf0;

    __shared__ float red[4];

    float s = nf0 * nf0;
#pragma unroll
    for (int o = 16; o > 0; o >>= 1) s += __shfl_xor_sync(0xffffffffu, s, o);
    if ((tid & 31) == 0) red[tid >> 5] = s;
    __syncthreads();
    float n1 = sqrtf(red[0] + red[1] + red[2] + red[3]);
    float nf1 = nf0 / n1;
    __syncthreads();

    s = nf1 * nf1;
#pragma unroll
    for (int o = 16; o > 0; o >>= 1) s += __shfl_xor_sync(0xffffffffu, s, o);
    if ((tid & 31) == 0) red[tid >> 5] = s;
    __syncthreads();
    float n2 = sqrtf(red[0] + red[1] + red[2] + red[3]);
    float nf = nf1 / n2;

    const size_t base = (size_t)row * 2 * FDIM;
    g_q[base + tid]        = nf;
    g_q[base + FDIM + tid] = diff;
    g_p[base + tid]        = a * nf;
    g_p[base + FDIM + tid] = (g * (1.0f / (float)FDIM)) * diff;
    if (tid == 0) g_beta[row] = b;
}

// ---------------------------------------------------------------------------
// CSR build: zero counts -> histogram -> scan -> fill
// ---------------------------------------------------------------------------
__global__ void zero_cnt_kernel()
{
    int i = blockIdx.x * blockDim.x + threadIdx.x;
    if (i < AGENTS) { g_act_cnt[i] = 0; g_cost_cnt[i] = 0; }
}

__global__ void hist_kernel(const int* __restrict__ act_src,
                            const int* __restrict__ edge_src)
{
    int e = blockIdx.x * blockDim.x + threadIdx.x;
    if (e < EDGES) {
        atomicAdd(&g_act_cnt[act_src[e]], 1);
        atomicAdd(&g_cost_cnt[edge_src[e]], 1);
    }
}

// Single block, 1024 threads. Exclusive scan of both count arrays (8192 each).
__global__ void __launch_bounds__(1024) scan_kernel()
{
    __shared__ int sh[1024];
    const int t = threadIdx.x;

#pragma unroll
    for (int which = 0; which < 2; which++) {
        const int* cnt = which ? g_cost_cnt : g_act_cnt;
        int* off = which ? g_cost_off : g_act_off;
        int* cur = which ? g_cost_cur : g_act_cur;

        int local[8];
        int tsum = 0;
        const int base = t * 8;
#pragma unroll
        for (int j = 0; j < 8; j++) { local[j] = cnt[base + j]; tsum += local[j]; }

        sh[t] = tsum;
        __syncthreads();
        // Hillis-Steele inclusive scan
        for (int o = 1; o < 1024; o <<= 1) {
            int v = (t >= o) ? sh[t - o] : 0;
            __syncthreads();
            sh[t] += v;
            __syncthreads();
        }
        int run = sh[t] - tsum;  // exclusive prefix for this thread
#pragma unroll
        for (int j = 0; j < 8; j++) {
            off[base + j] = run;
            cur[base + j] = run;
            run += local[j];
        }
        __syncthreads();
    }
}

__global__ void fill_kernel(const int* __restrict__ act_src,
                            const int* __restrict__ act_dst,
                            const int* __restrict__ edge_src,
                            const int* __restrict__ edge_dst)
{
    int e = blockIdx.x * blockDim.x + threadIdx.x;
    if (e < EDGES) {
        int p = atomicAdd(&g_act_cur[act_src[e]], 1);
        g_act_dst[p] = act_dst[e];
        p = atomicAdd(&g_cost_cur[edge_src[e]], 1);
        g_cost_dst[p] = edge_dst[e];
    }
}

// ---------------------------------------------------------------------------
// Fused kernel: one block per output row.
//   phase 1: zero own 32KB row
//   phase 2: act edges of this row — warp-dot p_row . q[dst], atomicAdd
//   phase 3: cost edges of this row — atomicAdd(-beta_row)
// Row ownership makes zero->add ordering safe via __syncthreads.
// ---------------------------------------------------------------------------
__global__ void __launch_bounds__(256) fused_kernel(float* __restrict__ out)
{
    const int r    = blockIdx.x;
    const int tid  = threadIdx.x;
    const int lane = tid & 31;
    const int w    = tid >> 5;   // 0..7

    __shared__ float4 sp4[64];   // 256 floats: this row's p vector
    ((float*)sp4)[tid] = g_p[(size_t)r * 2 * FDIM + tid];

    const float beta_r = g_beta[r];
    float* __restrict__ row = out + (size_t)r * AGENTS;

    // zero row: 8192 floats = 2048 float4, 8 per thread
    float4* row4 = (float4*)row;
    const float4 z = make_float4(0.f, 0.f, 0.f, 0.f);
#pragma unroll
    for (int i = 0; i < 8; i++) row4[tid + 256 * i] = z;
    __syncthreads();

    // act edges
    {
        const int off = g_act_off[r];
        const int cnt = g_act_cnt[r];
        const float4 p0 = sp4[lane];
        const float4 p1 = sp4[lane + 32];
        for (int i = w; i < cnt; i += 8) {
            const int d = g_act_dst[off + i];
            const float4* __restrict__ qq = (const float4*)(g_q + (size_t)d * 2 * FDIM);
            const float4 q0 = qq[lane];
            const float4 q1 = qq[lane + 32];
            float acc = p0.x * q0.x;
            acc = fmaf(p0.y, q0.y, acc);
            acc = fmaf(p0.z, q0.z, acc);
            acc = fmaf(p0.w, q0.w, acc);
            acc = fmaf(p1.x, q1.x, acc);
            acc = fmaf(p1.y, q1.y, acc);
            acc = fmaf(p1.z, q1.z, acc);
            acc = fmaf(p1.w, q1.w, acc);
#pragma unroll
            for (int o = 16; o > 0; o >>= 1)
                acc += __shfl_xor_sync(0xffffffffu, acc, o);
            if (lane == 0) atomicAdd(&row[d], acc);
        }
    }

    // cost edges
    {
        const int off = g_cost_off[r];
        const int cnt = g_cost_cnt[r];
        for (int i = tid; i < cnt; i += 256)
            atomicAdd(&row[g_cost_dst[off + i]], -beta_r);
    }
}

// ---------------------------------------------------------------------------
extern "C" void kernel_launch(void* const* d_in, const int* in_sizes, int n_in,
                              void* d_out, int out_size)
{
    const float* feature      = (const float*)d_in[0];
    const float* next_feature = (const float*)d_in[1];
    const float* persona_t    = (const float*)d_in[2];
    const float* alpha        = (const float*)d_in[3];
    const float* beta         = (const float*)d_in[4];
    const float* gamma        = (const float*)d_in[5];
    const int*   act_src      = (const int*)d_in[6];
    const int*   act_dst      = (const int*)d_in[7];
    const int*   edge_src     = (const int*)d_in[8];
    const int*   edge_dst     = (const int*)d_in[9];
    float* out = (float*)d_out;

    prep_kernel<<<AGENTS, 128>>>(feature, next_feature, persona_t,
                                 alpha, beta, gamma);

    zero_cnt_kernel<<<AGENTS / 256, 256>>>();
    hist_kernel<<<EDGES / 256, 256>>>(act_src, edge_src);
    scan_kernel<<<1, 1024>>>();
    fill_kernel<<<EDGES / 256, 256>>>(act_src, act_dst, edge_src, edge_dst);

    fused_kernel<<<AGENTS, 256>>>(out);
}

// round 3
// speedup vs baseline: 1.2418x; 1.2418x over previous
#include <cuda_runtime.h>
#include <cstddef>

#define AGENTS 8192
#define FDIM   128
#define PDIM   16
#define EDGES  262144
#define CAP    128          // max edges per source row (mean 32; P(>128) ~ e^-81)

// Scratch: packed per-row vectors (256 floats = 1KB per row).
// g_p[i] = [ alpha_i * nf_i | (gamma_i/F) * diff_i ]   (src side)
// g_q[i] = [ nf_i           | diff_i ]                 (dst side)
__device__ float g_p[(size_t)AGENTS * 2 * FDIM];
__device__ float g_q[(size_t)AGENTS * 2 * FDIM];
__device__ float g_beta[AGENTS];

// Slot-array CSR (no scan needed)
__device__ int g_act_cnt[AGENTS];
__device__ int g_cost_cnt[AGENTS];
__device__ int g_act_slot[(size_t)AGENTS * CAP];
__device__ int g_cost_slot[(size_t)AGENTS * CAP];

// ---------------------------------------------------------------------------
// Kernel 1: per-row prep (also zeroes this row's slot counters).
// ---------------------------------------------------------------------------
__global__ void __launch_bounds__(128) prep_kernel(
    const float* __restrict__ feature,
    const float* __restrict__ next_feature,
    const float* __restrict__ persona,
    const float* __restrict__ alpha,
    const float* __restrict__ beta,
    const float* __restrict__ gamma)
{
    const int row = blockIdx.x;
    const int tid = threadIdx.x;  // 0..127

    if (tid == 0) { g_act_cnt[row] = 0; g_cost_cnt[row] = 0; }

    float a = 0.f, b = 0.f, g = 0.f;
#pragma unroll
    for (int k = 0; k < PDIM; k++) {
        float pv = persona[row * PDIM + k];
        a = fmaf(pv, alpha[k], a);
        b = fmaf(pv, beta[k],  b);
        g = fmaf(pv, gamma[k], g);
    }

    const float f   = feature[(size_t)row * FDIM + tid];
    const float nf0 = next_feature[(size_t)row * FDIM + tid];
    const float diff = f - nf0;

    __shared__ float red[4];

    float s = nf0 * nf0;
#pragma unroll
    for (int o = 16; o > 0; o >>= 1) s += __shfl_xor_sync(0xffffffffu, s, o);
    if ((tid & 31) == 0) red[tid >> 5] = s;
    __syncthreads();
    float n1 = sqrtf(red[0] + red[1] + red[2] + red[3]);
    float nf1 = nf0 / n1;
    __syncthreads();

    s = nf1 * nf1;
#pragma unroll
    for (int o = 16; o > 0; o >>= 1) s += __shfl_xor_sync(0xffffffffu, s, o);
    if ((tid & 31) == 0) red[tid >> 5] = s;
    __syncthreads();
    float n2 = sqrtf(red[0] + red[1] + red[2] + red[3]);
    float nf = nf1 / n2;

    const size_t base = (size_t)row * 2 * FDIM;
    g_q[base + tid]        = nf;
    g_q[base + FDIM + tid] = diff;
    g_p[base + tid]        = a * nf;
    g_p[base + FDIM + tid] = (g * (1.0f / (float)FDIM)) * diff;
    if (tid == 0) g_beta[row] = b;
}

// ---------------------------------------------------------------------------
// Kernel 2: bucket both edge lists by src into fixed-capacity slot arrays.
// ---------------------------------------------------------------------------
__global__ void __launch_bounds__(256) fill_kernel(
    const int* __restrict__ act_src,
    const int* __restrict__ act_dst,
    const int* __restrict__ edge_src,
    const int* __restrict__ edge_dst)
{
    int e = blockIdx.x * blockDim.x + threadIdx.x;
    if (e >= EDGES) return;
    {
        int s = act_src[e];
        int slot = atomicAdd(&g_act_cnt[s], 1);
        g_act_slot[(size_t)s * CAP + slot] = act_dst[e];
    }
    {
        int s = edge_src[e];
        int slot = atomicAdd(&g_cost_cnt[s], 1);
        g_cost_slot[(size_t)s * CAP + slot] = edge_dst[e];
    }
}

// ---------------------------------------------------------------------------
// Kernel 3: one block per output row.
//   - zero a 32KB SMEM row buffer (no global traffic)
//   - act edges: warp-dot p_row(SMEM) . q[dst](L2 gather), atomicAdd to SMEM
//   - cost edges: atomicAdd(-beta_r) to SMEM
//   - stream the finished row to GMEM once (__stcs, evict-first)
// ---------------------------------------------------------------------------
__global__ void __launch_bounds__(256) fused_kernel(float* __restrict__ out)
{
    const int r    = blockIdx.x;
    const int tid  = threadIdx.x;
    const int lane = tid & 31;
    const int w    = tid >> 5;   // 0..7

    __shared__ float  srow[AGENTS];   // 32KB row accumulator
    __shared__ float4 sp4[64];        // 1KB: this row's p vector

    // zero smem row buffer
    float4* srow4 = (float4*)srow;
    const float4 z = make_float4(0.f, 0.f, 0.f, 0.f);
#pragma unroll
    for (int i = 0; i < 8; i++) srow4[tid + 256 * i] = z;
    ((float*)sp4)[tid] = g_p[(size_t)r * 2 * FDIM + tid];
    __syncthreads();

    // act edges: warps stride the row's edge list, 2-edge unroll for MLP
    {
        const int cnt = g_act_cnt[r];
        const int* __restrict__ dsts = g_act_slot + (size_t)r * CAP;
        const float4 p0 = sp4[lane];
        const float4 p1 = sp4[lane + 32];

        int i = w;
        for (; i + 8 < cnt; i += 16) {
            const int dA = dsts[i];
            const int dB = dsts[i + 8];
            const float4* __restrict__ qa = (const float4*)(g_q + (size_t)dA * 2 * FDIM);
            const float4* __restrict__ qb = (const float4*)(g_q + (size_t)dB * 2 * FDIM);
            float4 a0 = qa[lane];
            float4 a1 = qa[lane + 32];
            float4 b0 = qb[lane];
            float4 b1 = qb[lane + 32];

            float accA = p0.x * a0.x;
            float accB = p0.x * b0.x;
            accA = fmaf(p0.y, a0.y, accA);  accB = fmaf(p0.y, b0.y, accB);
            accA = fmaf(p0.z, a0.z, accA);  accB = fmaf(p0.z, b0.z, accB);
            accA = fmaf(p0.w, a0.w, accA);  accB = fmaf(p0.w, b0.w, accB);
            accA = fmaf(p1.x, a1.x, accA);  accB = fmaf(p1.x, b1.x, accB);
            accA = fmaf(p1.y, a1.y, accA);  accB = fmaf(p1.y, b1.y, accB);
            accA = fmaf(p1.z, a1.z, accA);  accB = fmaf(p1.z, b1.z, accB);
            accA = fmaf(p1.w, a1.w, accA);  accB = fmaf(p1.w, b1.w, accB);
#pragma unroll
            for (int o = 16; o > 0; o >>= 1) {
                accA += __shfl_xor_sync(0xffffffffu, accA, o);
                accB += __shfl_xor_sync(0xffffffffu, accB, o);
            }
            if (lane == 0) {
                atomicAdd(&srow[dA], accA);
                atomicAdd(&srow[dB], accB);
            }
        }
        for (; i < cnt; i += 8) {
            const int d = dsts[i];
            const float4* __restrict__ qq = (const float4*)(g_q + (size_t)d * 2 * FDIM);
            float4 q0 = qq[lane];
            float4 q1 = qq[lane + 32];
            float acc = p0.x * q0.x;
            acc = fmaf(p0.y, q0.y, acc);
            acc = fmaf(p0.z, q0.z, acc);
            acc = fmaf(p0.w, q0.w, acc);
            acc = fmaf(p1.x, q1.x, acc);
            acc = fmaf(p1.y, q1.y, acc);
            acc = fmaf(p1.z, q1.z, acc);
            acc = fmaf(p1.w, q1.w, acc);
#pragma unroll
            for (int o = 16; o > 0; o >>= 1)
                acc += __shfl_xor_sync(0xffffffffu, acc, o);
            if (lane == 0) atomicAdd(&srow[d], acc);
        }
    }

    // cost edges
    {
        const float beta_r = g_beta[r];
        const int cnt = g_cost_cnt[r];
        const int* __restrict__ dsts = g_cost_slot + (size_t)r * CAP;
        for (int i = tid; i < cnt; i += 256)
            atomicAdd(&srow[dsts[i]], -beta_r);
    }

    __syncthreads();

    // stream finished row to GMEM (evict-first: output is write-once)
    float4* __restrict__ row4 = (float4*)(out + (size_t)r * AGENTS);
#pragma unroll
    for (int i = 0; i < 8; i++)
        __stcs(&row4[tid + 256 * i], srow4[tid + 256 * i]);
}

// ---------------------------------------------------------------------------
extern "C" void kernel_launch(void* const* d_in, const int* in_sizes, int n_in,
                              void* d_out, int out_size)
{
    const float* feature      = (const float*)d_in[0];
    const float* next_feature = (const float*)d_in[1];
    const float* persona_t    = (const float*)d_in[2];
    const float* alpha        = (const float*)d_in[3];
    const float* beta         = (const float*)d_in[4];
    const float* gamma        = (const float*)d_in[5];
    const int*   act_src      = (const int*)d_in[6];
    const int*   act_dst      = (const int*)d_in[7];
    const int*   edge_src     = (const int*)d_in[8];
    const int*   edge_dst     = (const int*)d_in[9];
    float* out = (float*)d_out;

    prep_kernel<<<AGENTS, 128>>>(feature, next_feature, persona_t,
                                 alpha, beta, gamma);
    fill_kernel<<<EDGES / 256, 256>>>(act_src, act_dst, edge_src, edge_dst);
    fused_kernel<<<AGENTS, 256>>>(out);
}

// round 4
// speedup vs baseline: 1.6848x; 1.3567x over previous
#include <cuda_runtime.h>
#include <cstdint>
#include <cstddef>

#define AGENTS 8192
#define FDIM   128
#define PDIM   16
#define EDGES  262144
#define CAP    128          // max edges per source row (mean 32; P(>128) ~ e^-81)

// Scratch: packed per-row vectors (256 floats = 1KB per row).
// g_p[i] = [ alpha_i * nf_i | (gamma_i/F) * diff_i ]   (src side)
// g_q[i] = [ nf_i           | diff_i ]                 (dst side)
__device__ float g_p[(size_t)AGENTS * 2 * FDIM];
__device__ float g_q[(size_t)AGENTS * 2 * FDIM];
__device__ float g_beta[AGENTS];

// Slot-array CSR. Counters are zero at module load and are RESET by
// fused_kernel after consumption, so each launch sees zeros.
__device__ int g_act_cnt[AGENTS];
__device__ int g_cost_cnt[AGENTS];
__device__ int g_act_slot[(size_t)AGENTS * CAP];
__device__ int g_cost_slot[(size_t)AGENTS * CAP];

// ---------------------------------------------------------------------------
// Kernel 1 (combined): blocks [0,1024) = prep (warp-per-row, 8 rows/block),
//                      blocks [1024,2048) = edge bucketing (1 edge/thread).
// ---------------------------------------------------------------------------
__global__ void __launch_bounds__(256) pre_kernel(
    const float* __restrict__ feature,
    const float* __restrict__ next_feature,
    const float* __restrict__ persona,
    const float* __restrict__ alpha,
    const float* __restrict__ beta,
    const float* __restrict__ gamma,
    const int* __restrict__ act_src,
    const int* __restrict__ act_dst,
    const int* __restrict__ edge_src,
    const int* __restrict__ edge_dst)
{
    const int tid = threadIdx.x;

    if (blockIdx.x >= 1024) {
        // ---- fill part ----
        const int e = (blockIdx.x - 1024) * 256 + tid;   // exactly covers EDGES
        {
            int s = act_src[e];
            int slot = atomicAdd(&g_act_cnt[s], 1);
            g_act_slot[(size_t)s * CAP + slot] = act_dst[e];
        }
        {
            int s = edge_src[e];
            int slot = atomicAdd(&g_cost_cnt[s], 1);
            g_cost_slot[(size_t)s * CAP + slot] = edge_dst[e];
        }
        return;
    }

    // ---- prep part: one warp per row ----
    const int lane = tid & 31;
    const int row  = blockIdx.x * 8 + (tid >> 5);

    const float4 f4 = ((const float4*)feature)[row * 32 + lane];
    const float4 n4 = ((const float4*)next_feature)[row * 32 + lane];
    float4 diff;
    diff.x = f4.x - n4.x; diff.y = f4.y - n4.y;
    diff.z = f4.z - n4.z; diff.w = f4.w - n4.w;

    // persona-weighted scalars (vector loads, redundant per lane — L1 broadcast)
    float a = 0.f, b = 0.f, g = 0.f;
    const float4* __restrict__ pr = (const float4*)(persona + row * PDIM);
    const float4* __restrict__ al = (const float4*)alpha;
    const float4* __restrict__ be = (const float4*)beta;
    const float4* __restrict__ ga = (const float4*)gamma;
#pragma unroll
    for (int j = 0; j < 4; j++) {
        const float4 pv = pr[j];
        const float4 av = al[j], bv = be[j], gv = ga[j];
        a = fmaf(pv.x, av.x, fmaf(pv.y, av.y, fmaf(pv.z, av.z, fmaf(pv.w, av.w, a))));
        b = fmaf(pv.x, bv.x, fmaf(pv.y, bv.y, fmaf(pv.z, bv.z, fmaf(pv.w, bv.w, b))));
        g = fmaf(pv.x, gv.x, fmaf(pv.y, gv.y, fmaf(pv.z, gv.z, fmaf(pv.w, gv.w, g))));
    }

    // first L2 normalize
    float s = fmaf(n4.x, n4.x, fmaf(n4.y, n4.y, fmaf(n4.z, n4.z, n4.w * n4.w)));
#pragma unroll
    for (int o = 16; o > 0; o >>= 1) s += __shfl_xor_sync(0xffffffffu, s, o);
    const float n1 = sqrtf(s);
    float4 nf1;
    nf1.x = n4.x / n1; nf1.y = n4.y / n1; nf1.z = n4.z / n1; nf1.w = n4.w / n1;

    // second normalize (reference normalizes twice)
    s = fmaf(nf1.x, nf1.x, fmaf(nf1.y, nf1.y, fmaf(nf1.z, nf1.z, nf1.w * nf1.w)));
#pragma unroll
    for (int o = 16; o > 0; o >>= 1) s += __shfl_xor_sync(0xffffffffu, s, o);
    const float n2 = sqrtf(s);
    float4 nf;
    nf.x = nf1.x / n2; nf.y = nf1.y / n2; nf.z = nf1.z / n2; nf.w = nf1.w / n2;

    float4* __restrict__ q4 = (float4*)(g_q + (size_t)row * 2 * FDIM);
    float4* __restrict__ p4 = (float4*)(g_p + (size_t)row * 2 * FDIM);
    q4[lane]      = nf;
    q4[lane + 32] = diff;
    float4 pa, pg;
    pa.x = a * nf.x; pa.y = a * nf.y; pa.z = a * nf.z; pa.w = a * nf.w;
    const float gs = g * (1.0f / (float)FDIM);
    pg.x = gs * diff.x; pg.y = gs * diff.y; pg.z = gs * diff.z; pg.w = gs * diff.w;
    p4[lane]      = pa;
    p4[lane + 32] = pg;
    if (lane == 0) g_beta[row] = b;
}

// ---------------------------------------------------------------------------
// Kernel 2: one block per output row.
//   - zero 32KB SMEM row buffer
//   - act edges: warp-dot p_row . q[dst] (L2 gather), atomicAdd to SMEM
//   - cost edges: atomicAdd(-beta_r) to SMEM
//   - reset this row's counters (consumed), then one TMA bulk store to GMEM
// ---------------------------------------------------------------------------
__global__ void __launch_bounds__(256) fused_kernel(float* __restrict__ out)
{
    const int r    = blockIdx.x;
    const int tid  = threadIdx.x;
    const int lane = tid & 31;
    const int w    = tid >> 5;   // 0..7

    __shared__ float  srow[AGENTS];   // 32KB row accumulator
    __shared__ float4 sp4[64];        // 1KB: this row's p vector

    const int act_cnt  = g_act_cnt[r];
    const int cost_cnt = g_cost_cnt[r];

    // zero smem row buffer
    float4* srow4 = (float4*)srow;
    const float4 z = make_float4(0.f, 0.f, 0.f, 0.f);
#pragma unroll
    for (int i = 0; i < 8; i++) srow4[tid + 256 * i] = z;
    ((float*)sp4)[tid] = g_p[(size_t)r * 2 * FDIM + tid];
    __syncthreads();

    // act edges: warps stride the row's edge list, 2-edge unroll for MLP
    {
        const int* __restrict__ dsts = g_act_slot + (size_t)r * CAP;
        const float4 p0 = sp4[lane];
        const float4 p1 = sp4[lane + 32];

        int i = w;
        for (; i + 8 < act_cnt; i += 16) {
            const int dA = dsts[i];
            const int dB = dsts[i + 8];
            const float4* __restrict__ qa = (const float4*)(g_q + (size_t)dA * 2 * FDIM);
            const float4* __restrict__ qb = (const float4*)(g_q + (size_t)dB * 2 * FDIM);
            float4 a0 = qa[lane];
            float4 a1 = qa[lane + 32];
            float4 b0 = qb[lane];
            float4 b1 = qb[lane + 32];

            float accA = p0.x * a0.x;
            float accB = p0.x * b0.x;
            accA = fmaf(p0.y, a0.y, accA);  accB = fmaf(p0.y, b0.y, accB);
            accA = fmaf(p0.z, a0.z, accA);  accB = fmaf(p0.z, b0.z, accB);
            accA = fmaf(p0.w, a0.w, accA);  accB = fmaf(p0.w, b0.w, accB);
            accA = fmaf(p1.x, a1.x, accA);  accB = fmaf(p1.x, b1.x, accB);
            accA = fmaf(p1.y, a1.y, accA);  accB = fmaf(p1.y, b1.y, accB);
            accA = fmaf(p1.z, a1.z, accA);  accB = fmaf(p1.z, b1.z, accB);
            accA = fmaf(p1.w, a1.w, accA);  accB = fmaf(p1.w, b1.w, accB);
#pragma unroll
            for (int o = 16; o > 0; o >>= 1) {
                accA += __shfl_xor_sync(0xffffffffu, accA, o);
                accB += __shfl_xor_sync(0xffffffffu, accB, o);
            }
            if (lane == 0) {
                atomicAdd(&srow[dA], accA);
                atomicAdd(&srow[dB], accB);
            }
        }
        for (; i < act_cnt; i += 8) {
            const int d = dsts[i];
            const float4* __restrict__ qq = (const float4*)(g_q + (size_t)d * 2 * FDIM);
            float4 q0 = qq[lane];
            float4 q1 = qq[lane + 32];
            float acc = p0.x * q0.x;
            acc = fmaf(p0.y, q0.y, acc);
            acc = fmaf(p0.z, q0.z, acc);
            acc = fmaf(p0.w, q0.w, acc);
            acc = fmaf(p1.x, q1.x, acc);
            acc = fmaf(p1.y, q1.y, acc);
            acc = fmaf(p1.z, q1.z, acc);
            acc = fmaf(p1.w, q1.w, acc);
#pragma unroll
            for (int o = 16; o > 0; o >>= 1)
                acc += __shfl_xor_sync(0xffffffffu, acc, o);
            if (lane == 0) atomicAdd(&srow[d], acc);
        }
    }

    // cost edges
    {
        const float beta_r = g_beta[r];
        const int* __restrict__ dsts = g_cost_slot + (size_t)r * CAP;
        for (int i = tid; i < cost_cnt; i += 256)
            atomicAdd(&srow[dsts[i]], -beta_r);
    }

    __syncthreads();

    // reset consumed counters for the next launch (after all reads)
    if (tid == 0) { g_act_cnt[r] = 0; g_cost_cnt[r] = 0; }

    // single TMA bulk store of the finished 32KB row, evict-first
    if (tid == 0) {
        uint32_t saddr;
        asm("{ .reg .u64 t; cvta.to.shared.u64 t, %1; cvt.u32.u64 %0, t; }"
            : "=r"(saddr) : "l"((const void*)srow));
        float* gptr = out + (size_t)r * AGENTS;
        uint64_t policy;
        asm("createpolicy.fractional.L2::evict_first.b64 %0, 1.0;" : "=l"(policy));
        asm volatile("fence.proxy.async.shared::cta;" ::: "memory");
        asm volatile(
            "cp.async.bulk.global.shared::cta.bulk_group.L2::cache_hint "
            "[%0], [%1], %2, %3;"
            :: "l"(gptr), "r"(saddr), "r"((int)(AGENTS * 4)), "l"(policy)
            : "memory");
        asm volatile("cp.async.bulk.commit_group;" ::: "memory");
        asm volatile("cp.async.bulk.wait_group 0;" ::: "memory");
    }
}

// ---------------------------------------------------------------------------
extern "C" void kernel_launch(void* const* d_in, const int* in_sizes, int n_in,
                              void* d_out, int out_size)
{
    const float* feature      = (const float*)d_in[0];
    const float* next_feature = (const float*)d_in[1];
    const float* persona_t    = (const float*)d_in[2];
    const float* alpha        = (const float*)d_in[3];
    const float* beta         = (const float*)d_in[4];
    const float* gamma        = (const float*)d_in[5];
    const int*   act_src      = (const int*)d_in[6];
    const int*   act_dst      = (const int*)d_in[7];
    const int*   edge_src     = (const int*)d_in[8];
    const int*   edge_dst     = (const int*)d_in[9];
    float* out = (float*)d_out;

    pre_kernel<<<2048, 256>>>(feature, next_feature, persona_t,
                              alpha, beta, gamma,
                              act_src, act_dst, edge_src, edge_dst);
    fused_kernel<<<AGENTS, 256>>>(out);
}

// round 5
// speedup vs baseline: 1.8688x; 1.1092x over previous
#include <cuda_runtime.h>
#include <cuda_fp16.h>
#include <cstdint>
#include <cstddef>

#define AGENTS 8192
#define FDIM   128
#define PDIM   16
#define EDGES  262144
#define CAP    128          // max edges per source row (mean 32; P(>128) ~ e^-81)

// Per-row packed vectors.
// g_p[i]  (fp32): [ alpha_i * nf_i | (gamma_i/F) * diff_i ]   (src side)
// g_qh[i] (fp16): [ nf_i           | diff_i ]                 (dst side, gathered)
__device__ float  g_p[(size_t)AGENTS * 2 * FDIM];
__device__ __half g_qh[(size_t)AGENTS * 2 * FDIM];
__device__ float  g_beta[AGENTS];

// Slot-array CSR. Counters zero at load; RESET by fused_kernel after use.
__device__ int g_act_cnt[AGENTS];
__device__ int g_cost_cnt[AGENTS];
__device__ int g_act_slot[(size_t)AGENTS * CAP];
__device__ int g_cost_slot[(size_t)AGENTS * CAP];

// ---------------------------------------------------------------------------
// Kernel 1 (combined): blocks [0,1024) = prep (warp-per-row, 8 rows/block),
//                      blocks [1024,2048) = edge bucketing (1 edge/thread).
// ---------------------------------------------------------------------------
__global__ void __launch_bounds__(256) pre_kernel(
    const float* __restrict__ feature,
    const float* __restrict__ next_feature,
    const float* __restrict__ persona,
    const float* __restrict__ alpha,
    const float* __restrict__ beta,
    const float* __restrict__ gamma,
    const int* __restrict__ act_src,
    const int* __restrict__ act_dst,
    const int* __restrict__ edge_src,
    const int* __restrict__ edge_dst)
{
    const int tid = threadIdx.x;

    if (blockIdx.x >= 1024) {
        const int e = (blockIdx.x - 1024) * 256 + tid;   // exactly covers EDGES
        {
            int s = act_src[e];
            int slot = atomicAdd(&g_act_cnt[s], 1);
            g_act_slot[(size_t)s * CAP + slot] = act_dst[e];
        }
        {
            int s = edge_src[e];
            int slot = atomicAdd(&g_cost_cnt[s], 1);
            g_cost_slot[(size_t)s * CAP + slot] = edge_dst[e];
        }
        return;
    }

    // ---- prep: one warp per row ----
    const int lane = tid & 31;
    const int row  = blockIdx.x * 8 + (tid >> 5);

    const float4 f4 = ((const float4*)feature)[row * 32 + lane];
    const float4 n4 = ((const float4*)next_feature)[row * 32 + lane];
    float4 diff;
    diff.x = f4.x - n4.x; diff.y = f4.y - n4.y;
    diff.z = f4.z - n4.z; diff.w = f4.w - n4.w;

    float a = 0.f, b = 0.f, g = 0.f;
    const float4* __restrict__ pr = (const float4*)(persona + row * PDIM);
    const float4* __restrict__ al = (const float4*)alpha;
    const float4* __restrict__ be = (const float4*)beta;
    const float4* __restrict__ ga = (const float4*)gamma;
#pragma unroll
    for (int j = 0; j < 4; j++) {
        const float4 pv = pr[j];
        const float4 av = al[j], bv = be[j], gv = ga[j];
        a = fmaf(pv.x, av.x, fmaf(pv.y, av.y, fmaf(pv.z, av.z, fmaf(pv.w, av.w, a))));
        b = fmaf(pv.x, bv.x, fmaf(pv.y, bv.y, fmaf(pv.z, bv.z, fmaf(pv.w, bv.w, b))));
        g = fmaf(pv.x, gv.x, fmaf(pv.y, gv.y, fmaf(pv.z, gv.z, fmaf(pv.w, gv.w, g))));
    }

    // double L2 normalize (reference normalizes twice)
    float s = fmaf(n4.x, n4.x, fmaf(n4.y, n4.y, fmaf(n4.z, n4.z, n4.w * n4.w)));
#pragma unroll
    for (int o = 16; o > 0; o >>= 1) s += __shfl_xor_sync(0xffffffffu, s, o);
    const float n1 = sqrtf(s);
    float4 nf1;
    nf1.x = n4.x / n1; nf1.y = n4.y / n1; nf1.z = n4.z / n1; nf1.w = n4.w / n1;

    s = fmaf(nf1.x, nf1.x, fmaf(nf1.y, nf1.y, fmaf(nf1.z, nf1.z, nf1.w * nf1.w)));
#pragma unroll
    for (int o = 16; o > 0; o >>= 1) s += __shfl_xor_sync(0xffffffffu, s, o);
    const float n2 = sqrtf(s);
    float4 nf;
    nf.x = nf1.x / n2; nf.y = nf1.y / n2; nf.z = nf1.z / n2; nf.w = nf1.w / n2;

    // q in fp16: [nf | diff]
    __half2* __restrict__ qh2 = (__half2*)(g_qh + (size_t)row * 2 * FDIM);
    qh2[2 * lane]          = __floats2half2_rn(nf.x, nf.y);
    qh2[2 * lane + 1]      = __floats2half2_rn(nf.z, nf.w);
    qh2[64 + 2 * lane]     = __floats2half2_rn(diff.x, diff.y);
    qh2[64 + 2 * lane + 1] = __floats2half2_rn(diff.z, diff.w);

    // p in fp32: [a*nf | (g/F)*diff]
    float4* __restrict__ p4 = (float4*)(g_p + (size_t)row * 2 * FDIM);
    float4 pa, pg;
    pa.x = a * nf.x; pa.y = a * nf.y; pa.z = a * nf.z; pa.w = a * nf.w;
    const float gs = g * (1.0f / (float)FDIM);
    pg.x = gs * diff.x; pg.y = gs * diff.y; pg.z = gs * diff.z; pg.w = gs * diff.w;
    p4[lane]      = pa;
    p4[lane + 32] = pg;
    if (lane == 0) g_beta[row] = b;
}

// ---------------------------------------------------------------------------
// Kernel 2: one block per output row.
// Dot layout: lane L owns elements [8L, 8L+8) of the 256-dim vectors.
//   p: float4 indices 2L, 2L+1   |   q: one uint4 (8 halves) at index L.
// ---------------------------------------------------------------------------
__device__ __forceinline__ float dot8(const float4 p0, const float4 p1, const uint4 qv)
{
    const __half2 h0 = *(const __half2*)&qv.x;
    const __half2 h1 = ((const __half2*)&qv.x)[1];
    const __half2 h2 = *(const __half2*)&qv.z;
    const __half2 h3 = ((const __half2*)&qv.z)[1];
    const float2 f0 = __half22float2(h0);
    const float2 f1 = __half22float2(h1);
    const float2 f2 = __half22float2(h2);
    const float2 f3 = __half22float2(h3);
    float acc = p0.x * f0.x;
    acc = fmaf(p0.y, f0.y, acc);
    acc = fmaf(p0.z, f1.x, acc);
    acc = fmaf(p0.w, f1.y, acc);
    acc = fmaf(p1.x, f2.x, acc);
    acc = fmaf(p1.y, f2.y, acc);
    acc = fmaf(p1.z, f3.x, acc);
    acc = fmaf(p1.w, f3.y, acc);
    return acc;
}

__global__ void __launch_bounds__(256) fused_kernel(float* __restrict__ out)
{
    const int r    = blockIdx.x;
    const int tid  = threadIdx.x;
    const int lane = tid & 31;
    const int w    = tid >> 5;   // 0..7

    __shared__ float srow[AGENTS];   // 32KB row accumulator

    const int act_cnt  = g_act_cnt[r];
    const int cost_cnt = g_cost_cnt[r];

    // zero smem row buffer
    float4* srow4 = (float4*)srow;
    const float4 z = make_float4(0.f, 0.f, 0.f, 0.f);
#pragma unroll
    for (int i = 0; i < 8; i++) srow4[tid + 256 * i] = z;

    // this row's p slice for this lane (global load; L1-broadcast across warps)
    const float4* __restrict__ pp = (const float4*)(g_p + (size_t)r * 2 * FDIM);
    const float4 p0 = __ldg(&pp[2 * lane]);
    const float4 p1 = __ldg(&pp[2 * lane + 1]);
    __syncthreads();

    // act edges: warps stride the row's list, 2-edge unroll for MLP
    {
        const int* __restrict__ dsts = g_act_slot + (size_t)r * CAP;
        int i = w;
        for (; i + 8 < act_cnt; i += 16) {
            const int dA = dsts[i];
            const int dB = dsts[i + 8];
            const uint4 qa = __ldg((const uint4*)(g_qh + (size_t)dA * 2 * FDIM) + lane);
            const uint4 qb = __ldg((const uint4*)(g_qh + (size_t)dB * 2 * FDIM) + lane);
            float accA = dot8(p0, p1, qa);
            float accB = dot8(p0, p1, qb);
#pragma unroll
            for (int o = 16; o > 0; o >>= 1) {
                accA += __shfl_xor_sync(0xffffffffu, accA, o);
                accB += __shfl_xor_sync(0xffffffffu, accB, o);
            }
            if (lane == 0) {
                atomicAdd(&srow[dA], accA);
                atomicAdd(&srow[dB], accB);
            }
        }
        for (; i < act_cnt; i += 8) {
            const int d = dsts[i];
            const uint4 qv = __ldg((const uint4*)(g_qh + (size_t)d * 2 * FDIM) + lane);
            float acc = dot8(p0, p1, qv);
#pragma unroll
            for (int o = 16; o > 0; o >>= 1)
                acc += __shfl_xor_sync(0xffffffffu, acc, o);
            if (lane == 0) atomicAdd(&srow[d], acc);
        }
    }

    // cost edges
    {
        const float beta_r = g_beta[r];
        const int* __restrict__ dsts = g_cost_slot + (size_t)r * CAP;
        for (int i = tid; i < cost_cnt; i += 256)
            atomicAdd(&srow[dsts[i]], -beta_r);
    }

    __syncthreads();

    // reset consumed counters for the next launch (after all reads)
    if (tid == 0) { g_act_cnt[r] = 0; g_cost_cnt[r] = 0; }

    // single TMA bulk store of the finished 32KB row, evict-first
    if (tid == 0) {
        uint32_t saddr;
        asm("{ .reg .u64 t; cvta.to.shared.u64 t, %1; cvt.u32.u64 %0, t; }"
            : "=r"(saddr) : "l"((const void*)srow));
        float* gptr = out + (size_t)r * AGENTS;
        uint64_t policy;
        asm("createpolicy.fractional.L2::evict_first.b64 %0, 1.0;" : "=l"(policy));
        asm volatile("fence.proxy.async.shared::cta;" ::: "memory");
        asm volatile(
            "cp.async.bulk.global.shared::cta.bulk_group.L2::cache_hint "
            "[%0], [%1], %2, %3;"
            :: "l"(gptr), "r"(saddr), "r"((int)(AGENTS * 4)), "l"(policy)
            : "memory");
        asm volatile("cp.async.bulk.commit_group;" ::: "memory");
        asm volatile("cp.async.bulk.wait_group 0;" ::: "memory");
    }
}

// ---------------------------------------------------------------------------
extern "C" void kernel_launch(void* const* d_in, const int* in_sizes, int n_in,
                              void* d_out, int out_size)
{
    const float* feature      = (const float*)d_in[0];
    const float* next_feature = (const float*)d_in[1];
    const float* persona_t    = (const float*)d_in[2];
    const float* alpha        = (const float*)d_in[3];
    const float* beta         = (const float*)d_in[4];
    const float* gamma        = (const float*)d_in[5];
    const int*   act_src      = (const int*)d_in[6];
    const int*   act_dst      = (const int*)d_in[7];
    const int*   edge_src     = (const int*)d_in[8];
    const int*   edge_dst     = (const int*)d_in[9];
    float* out = (float*)d_out;

    pre_kernel<<<2048, 256>>>(feature, next_feature, persona_t,
                              alpha, beta, gamma,
                              act_src, act_dst, edge_src, edge_dst);
    fused_kernel<<<AGENTS, 256>>>(out);
}

// round 6
// speedup vs baseline: 1.8950x; 1.0140x over previous
#include <cuda_runtime.h>
#include <cuda_fp16.h>
#include <cstdint>
#include <cstddef>

#define AGENTS 8192
#define FDIM   128
#define PDIM   16
#define EDGES  262144
#define HALF   4096         // columns per half-row
#define NBUCK  (AGENTS * 2) // (row, half) buckets
#define CAP    96           // max edges per half-row (mean 16; P(>96) ~ 0)

// Per-row packed vectors.
// g_p[i]  (fp32): [ alpha_i * nf_i | (gamma_i/F) * diff_i ]   (src side)
// g_qh[i] (fp16): [ nf_i           | diff_i ]                 (dst side, gathered)
__device__ float  g_p[(size_t)AGENTS * 2 * FDIM];
__device__ __half g_qh[(size_t)AGENTS * 2 * FDIM];
__device__ float  g_beta[AGENTS];

// Slot-array CSR over (row, half) buckets. Counters zero at load; RESET by
// fused_kernel after consumption. Stored dst is already local (0..4095).
__device__ int g_act_cnt[NBUCK];
__device__ int g_cost_cnt[NBUCK];
__device__ int g_act_slot[(size_t)NBUCK * CAP];
__device__ int g_cost_slot[(size_t)NBUCK * CAP];

// ---------------------------------------------------------------------------
// Kernel 1 (combined): blocks [0,1024) = prep (warp-per-row, 8 rows/block),
//                      blocks [1024,2048) = edge bucketing (1 edge/thread).
// ---------------------------------------------------------------------------
__global__ void __launch_bounds__(256) pre_kernel(
    const float* __restrict__ feature,
    const float* __restrict__ next_feature,
    const float* __restrict__ persona,
    const float* __restrict__ alpha,
    const float* __restrict__ beta,
    const float* __restrict__ gamma,
    const int* __restrict__ act_src,
    const int* __restrict__ act_dst,
    const int* __restrict__ edge_src,
    const int* __restrict__ edge_dst)
{
    const int tid = threadIdx.x;

    if (blockIdx.x >= 1024) {
        const int e = (blockIdx.x - 1024) * 256 + tid;   // exactly covers EDGES
        {
            const int s = act_src[e];
            const int d = act_dst[e];
            const int bk = s * 2 + (d >> 12);
            const int slot = atomicAdd(&g_act_cnt[bk], 1);
            g_act_slot[(size_t)bk * CAP + slot] = d & (HALF - 1);
        }
        {
            const int s = edge_src[e];
            const int d = edge_dst[e];
            const int bk = s * 2 + (d >> 12);
            const int slot = atomicAdd(&g_cost_cnt[bk], 1);
            g_cost_slot[(size_t)bk * CAP + slot] = d & (HALF - 1);
        }
        return;
    }

    // ---- prep: one warp per row ----
    const int lane = tid & 31;
    const int row  = blockIdx.x * 8 + (tid >> 5);

    const float4 f4 = ((const float4*)feature)[row * 32 + lane];
    const float4 n4 = ((const float4*)next_feature)[row * 32 + lane];
    float4 diff;
    diff.x = f4.x - n4.x; diff.y = f4.y - n4.y;
    diff.z = f4.z - n4.z; diff.w = f4.w - n4.w;

    float a = 0.f, b = 0.f, g = 0.f;
    const float4* __restrict__ pr = (const float4*)(persona + row * PDIM);
    const float4* __restrict__ al = (const float4*)alpha;
    const float4* __restrict__ be = (const float4*)beta;
    const float4* __restrict__ ga = (const float4*)gamma;
#pragma unroll
    for (int j = 0; j < 4; j++) {
        const float4 pv = pr[j];
        const float4 av = al[j], bv = be[j], gv = ga[j];
        a = fmaf(pv.x, av.x, fmaf(pv.y, av.y, fmaf(pv.z, av.z, fmaf(pv.w, av.w, a))));
        b = fmaf(pv.x, bv.x, fmaf(pv.y, bv.y, fmaf(pv.z, bv.z, fmaf(pv.w, bv.w, b))));
        g = fmaf(pv.x, gv.x, fmaf(pv.y, gv.y, fmaf(pv.z, gv.z, fmaf(pv.w, gv.w, g))));
    }

    // double L2 normalize (reference normalizes twice)
    float s = fmaf(n4.x, n4.x, fmaf(n4.y, n4.y, fmaf(n4.z, n4.z, n4.w * n4.w)));
#pragma unroll
    for (int o = 16; o > 0; o >>= 1) s += __shfl_xor_sync(0xffffffffu, s, o);
    const float n1 = sqrtf(s);
    float4 nf1;
    nf1.x = n4.x / n1; nf1.y = n4.y / n1; nf1.z = n4.z / n1; nf1.w = n4.w / n1;

    s = fmaf(nf1.x, nf1.x, fmaf(nf1.y, nf1.y, fmaf(nf1.z, nf1.z, nf1.w * nf1.w)));
#pragma unroll
    for (int o = 16; o > 0; o >>= 1) s += __shfl_xor_sync(0xffffffffu, s, o);
    const float n2 = sqrtf(s);
    float4 nf;
    nf.x = nf1.x / n2; nf.y = nf1.y / n2; nf.z = nf1.z / n2; nf.w = nf1.w / n2;

    // q in fp16: [nf | diff]
    __half2* __restrict__ qh2 = (__half2*)(g_qh + (size_t)row * 2 * FDIM);
    qh2[2 * lane]          = __floats2half2_rn(nf.x, nf.y);
    qh2[2 * lane + 1]      = __floats2half2_rn(nf.z, nf.w);
    qh2[64 + 2 * lane]     = __floats2half2_rn(diff.x, diff.y);
    qh2[64 + 2 * lane + 1] = __floats2half2_rn(diff.z, diff.w);

    // p in fp32: [a*nf | (g/F)*diff]
    float4* __restrict__ p4 = (float4*)(g_p + (size_t)row * 2 * FDIM);
    float4 pa, pg;
    pa.x = a * nf.x; pa.y = a * nf.y; pa.z = a * nf.z; pa.w = a * nf.w;
    const float gs = g * (1.0f / (float)FDIM);
    pg.x = gs * diff.x; pg.y = gs * diff.y; pg.z = gs * diff.z; pg.w = gs * diff.w;
    p4[lane]      = pa;
    p4[lane + 32] = pg;
    if (lane == 0) g_beta[row] = b;
}

// ---------------------------------------------------------------------------
// Kernel 2: one block per HALF output row (16KB smem -> 8 blocks/SM, occ 100%).
// Dot layout: lane L owns elements [8L, 8L+8) of the 256-dim vectors.
// ---------------------------------------------------------------------------
__device__ __forceinline__ float dot8(const float4 p0, const float4 p1, const uint4 qv)
{
    const __half2 h0 = *(const __half2*)&qv.x;
    const __half2 h1 = ((const __half2*)&qv.x)[1];
    const __half2 h2 = *(const __half2*)&qv.z;
    const __half2 h3 = ((const __half2*)&qv.z)[1];
    const float2 f0 = __half22float2(h0);
    const float2 f1 = __half22float2(h1);
    const float2 f2 = __half22float2(h2);
    const float2 f3 = __half22float2(h3);
    float acc = p0.x * f0.x;
    acc = fmaf(p0.y, f0.y, acc);
    acc = fmaf(p0.z, f1.x, acc);
    acc = fmaf(p0.w, f1.y, acc);
    acc = fmaf(p1.x, f2.x, acc);
    acc = fmaf(p1.y, f2.y, acc);
    acc = fmaf(p1.z, f3.x, acc);
    acc = fmaf(p1.w, f3.y, acc);
    return acc;
}

__global__ void __launch_bounds__(256) fused_kernel(float* __restrict__ out)
{
    const int bk   = blockIdx.x;          // bucket = r*2 + half
    const int r    = bk >> 1;
    const int half = bk & 1;
    const int tid  = threadIdx.x;
    const int lane = tid & 31;
    const int w    = tid >> 5;   // 0..7

    __shared__ float srow[HALF];   // 16KB half-row accumulator

    const int act_cnt  = g_act_cnt[bk];
    const int cost_cnt = g_cost_cnt[bk];

    // zero smem half-row
    float4* srow4 = (float4*)srow;
    const float4 z = make_float4(0.f, 0.f, 0.f, 0.f);
#pragma unroll
    for (int i = 0; i < 4; i++) srow4[tid + 256 * i] = z;

    // this row's p slice for this lane (L1-broadcast across warps/blocks)
    const float4* __restrict__ pp = (const float4*)(g_p + (size_t)r * 2 * FDIM);
    const float4 p0 = __ldg(&pp[2 * lane]);
    const float4 p1 = __ldg(&pp[2 * lane + 1]);
    __syncthreads();

    // act edges: warps stride the bucket's list, 2-edge unroll for MLP
    {
        const int* __restrict__ dsts = g_act_slot + (size_t)bk * CAP;
        int i = w;
        for (; i + 8 < act_cnt; i += 16) {
            const int dA = dsts[i];
            const int dB = dsts[i + 8];
            // dst index is local; global row index = half*HALF + d
            const size_t gA = ((size_t)(half * HALF + dA)) * 2 * FDIM;
            const size_t gB = ((size_t)(half * HALF + dB)) * 2 * FDIM;
            const uint4 qa = __ldg((const uint4*)(g_qh + gA) + lane);
            const uint4 qb = __ldg((const uint4*)(g_qh + gB) + lane);
            float accA = dot8(p0, p1, qa);
            float accB = dot8(p0, p1, qb);
#pragma unroll
            for (int o = 16; o > 0; o >>= 1) {
                accA += __shfl_xor_sync(0xffffffffu, accA, o);
                accB += __shfl_xor_sync(0xffffffffu, accB, o);
            }
            if (lane == 0) {
                atomicAdd(&srow[dA], accA);
                atomicAdd(&srow[dB], accB);
            }
        }
        for (; i < act_cnt; i += 8) {
            const int d = dsts[i];
            const size_t gq = ((size_t)(half * HALF + d)) * 2 * FDIM;
            const uint4 qv = __ldg((const uint4*)(g_qh + gq) + lane);
            float acc = dot8(p0, p1, qv);
#pragma unroll
            for (int o = 16; o > 0; o >>= 1)
                acc += __shfl_xor_sync(0xffffffffu, acc, o);
            if (lane == 0) atomicAdd(&srow[d], acc);
        }
    }

    // cost edges
    {
        const float beta_r = g_beta[r];
        const int* __restrict__ dsts = g_cost_slot + (size_t)bk * CAP;
        for (int i = tid; i < cost_cnt; i += 256)
            atomicAdd(&srow[dsts[i]], -beta_r);
    }

    __syncthreads();

    // reset consumed counters for the next launch (after all reads)
    if (tid == 0) { g_act_cnt[bk] = 0; g_cost_cnt[bk] = 0; }

    // one TMA bulk store of the finished 16KB half-row, evict-first.
    // wait only for the smem READ side so the block retires while writes drain.
    if (tid == 0) {
        uint32_t saddr;
        asm("{ .reg .u64 t; cvta.to.shared.u64 t, %1; cvt.u32.u64 %0, t; }"
            : "=r"(saddr) : "l"((const void*)srow));
        float* gptr = out + (size_t)r * AGENTS + (size_t)half * HALF;
        uint64_t policy;
        asm("createpolicy.fractional.L2::evict_first.b64 %0, 1.0;" : "=l"(policy));
        asm volatile("fence.proxy.async.shared::cta;" ::: "memory");
        asm volatile(
            "cp.async.bulk.global.shared::cta.bulk_group.L2::cache_hint "
            "[%0], [%1], %2, %3;"
            :: "l"(gptr), "r"(saddr), "r"((int)(HALF * 4)), "l"(policy)
            : "memory");
        asm volatile("cp.async.bulk.commit_group;" ::: "memory");
        asm volatile("cp.async.bulk.wait_group.read 0;" ::: "memory");
    }
}

// ---------------------------------------------------------------------------
extern "C" void kernel_launch(void* const* d_in, const int* in_sizes, int n_in,
                              void* d_out, int out_size)
{
    const float* feature      = (const float*)d_in[0];
    const float* next_feature = (const float*)d_in[1];
    const float* persona_t    = (const float*)d_in[2];
    const float* alpha        = (const float*)d_in[3];
    const float* beta         = (const float*)d_in[4];
    const float* gamma        = (const float*)d_in[5];
    const int*   act_src      = (const int*)d_in[6];
    const int*   act_dst      = (const int*)d_in[7];
    const int*   edge_src     = (const int*)d_in[8];
    const int*   edge_dst     = (const int*)d_in[9];
    float* out = (float*)d_out;

    pre_kernel<<<2048, 256>>>(feature, next_feature, persona_t,
                              alpha, beta, gamma,
                              act_src, act_dst, edge_src, edge_dst);
    fused_kernel<<<NBUCK, 256>>>(out);
}